// round 12
// baseline (speedup 1.0000x reference)
#include <cuda_runtime.h>
#include <cuda_bf16.h>
#include <math.h>
#include <stdint.h>

#define BB 16
#define SS 512
#define DD 1024
#define NTOK (BB*SS)
#define NEG_BIG (-3.0e38f)
#define NPID 64
#define KS 4               // K-splits for pair phase
#define BK 32
#define NCH (DD / BK)
#define PCH (NCH / KS)     // chunks per pair K-split = 8
#define STR 40             // smem row stride in bf16 elems (80B, LDSM conflict-free)

// ------------------------------ scratch (static device globals; no allocs) --
__device__ float g_q[(size_t)NTOK * DD];
__device__ float g_k[(size_t)NTOK * DD];
__device__ float g_invn[NTOK];
__device__ int   g_idx0[NTOK];
__device__ int   g_idx1[NTOK];
__device__ int   g_cnt[2 * BB];
__device__ float g_pm[BB * NPID];
__device__ float g_pl[BB * NPID];
__device__ float g_pa[BB * NPID];
__device__ float g_partL[(size_t)BB * KS * NPID * 4096];
__device__ float g_partG[(size_t)BB * KS * NPID * 4096];

__device__ __forceinline__ void softmax_merge(float& m1, float& l1, float& a1,
                                              float m2, float l2, float a2) {
    float M  = fmaxf(m1, m2);
    float e1 = (l1 > 0.f) ? expf(m1 - M) : 0.f;
    float e2 = (l2 > 0.f) ? expf(m2 - M) : 0.f;
    l1 = l1 * e1 + l2 * e2;
    a1 = a1 * e1 + a2 * e2;
    m1 = M;
}

__device__ __forceinline__ uint32_t pack_bf2(float x, float y) {
    __nv_bfloat162 h = __floats2bfloat162_rn(x, y);
    return *(uint32_t*)&h;
}
__device__ __forceinline__ void mma16816(float* c, const uint32_t* a, const uint32_t* b) {
    asm volatile(
        "mma.sync.aligned.m16n8k16.row.col.f32.bf16.bf16.f32 "
        "{%0,%1,%2,%3}, {%4,%5,%6,%7}, {%8,%9}, {%0,%1,%2,%3};"
        : "+f"(c[0]), "+f"(c[1]), "+f"(c[2]), "+f"(c[3])
        : "r"(a[0]), "r"(a[1]), "r"(a[2]), "r"(a[3]), "r"(b[0]), "r"(b[1]));
}
__device__ __forceinline__ void ldsm4(uint32_t* r, uint32_t addr) {
    asm volatile("ldmatrix.sync.aligned.m8n8.x4.shared.b16 {%0,%1,%2,%3}, [%4];"
        : "=r"(r[0]), "=r"(r[1]), "=r"(r[2]), "=r"(r[3]) : "r"(addr));
}
__device__ __forceinline__ uint32_t smem_addr(const void* p) {
    return (uint32_t)__cvta_generic_to_shared(p);
}
__device__ __forceinline__ void split_store(uint16_t* hB, uint16_t* lB,
                                            int row, int seg, float4 v) {
    uint32_t h01 = pack_bf2(v.x, v.y), h23 = pack_bf2(v.z, v.w);
    __nv_bfloat162 a01 = *(__nv_bfloat162*)&h01, a23 = *(__nv_bfloat162*)&h23;
    uint32_t l01 = pack_bf2(v.x - __bfloat162float(a01.x), v.y - __bfloat162float(a01.y));
    uint32_t l23 = pack_bf2(v.z - __bfloat162float(a23.x), v.w - __bfloat162float(a23.y));
    uint32_t* dh = (uint32_t*)(hB + row * STR + seg * 4);
    uint32_t* dl = (uint32_t*)(lB + row * STR + seg * 4);
    dh[0] = h01; dh[1] = h23;
    dl[0] = l01; dl[1] = l23;
}

// ---------------- fused: row inv-norms (all blocks) + mask compaction -------
// grid = NTOK/16 blocks x 512 threads. Blocks 0..BB-1 also compact masks for
// batch b = blockIdx.x (independent outputs; both consumed by later kernels).
__global__ __launch_bounds__(512) void prep_and_norms(
    const float* __restrict__ E,
    const int* __restrict__ am, const int* __restrict__ tt)
{
    int row  = blockIdx.x * 16 + (threadIdx.x >> 5);
    int lane = threadIdx.x & 31;
    const float4* p = (const float4*)(E + (size_t)row * DD);
    float s = 0.f;
    #pragma unroll
    for (int i = 0; i < 8; i++) {
        float4 v = p[lane + i * 32];
        s += v.x * v.x + v.y * v.y + v.z * v.z + v.w * v.w;
    }
    #pragma unroll
    for (int o = 16; o > 0; o >>= 1) s += __shfl_down_sync(0xffffffffu, s, o);
    if (lane == 0) g_invn[row] = 1.f / fmaxf(sqrtf(s), 1e-12f);

    // mask compaction for batch = blockIdx.x (first BB blocks only)
    if (blockIdx.x < BB) {
        int b = blockIdx.x;
        int t = threadIdx.x;
        int w = t >> 5;
        int a  = am[b * SS + t];
        int ty = tt[b * SS + t];
        bool f0 = (a == 1) && (ty == 0);
        bool f1 = (a == 1) && (ty == 1);
        unsigned bal0 = __ballot_sync(0xffffffffu, f0);
        unsigned bal1 = __ballot_sync(0xffffffffu, f1);
        __shared__ int wc0[16], wc1[16], off0[16], off1[16];
        if (lane == 0) { wc0[w] = __popc(bal0); wc1[w] = __popc(bal1); }
        __syncthreads();
        if (t == 0) {
            int s0 = 0, s1 = 0;
            for (int i = 0; i < 16; i++) {
                off0[i] = s0; s0 += wc0[i];
                off1[i] = s1; s1 += wc1[i];
            }
            g_cnt[b] = s0; g_cnt[BB + b] = s1;
        }
        __syncthreads();
        if (f0) g_idx0[b * SS + off0[w] + __popc(bal0 & ((1u << lane) - 1u))] = t;
        if (f1) g_idx1[b * SS + off1[w] + __popc(bal1 & ((1u << lane) - 1u))] = t;
    }
}

// ---- mma.sync bf16x3 gathered projection GEMM (64-row tiles, double-buffer) --
#define PROJ_STAGE_B 30720            // bytes per stage: (64+64+128+128)*STR*2
#define PROJ_SMEM (2 * PROJ_STAGE_B)  // 61440

__global__ __launch_bounds__(256) void proj_mma(
    const float* __restrict__ E,
    const float* __restrict__ Wq, const float* __restrict__ bq,
    const float* __restrict__ Wk, const float* __restrict__ bk)
{
    int z = blockIdx.z;
    int b = z & 15, which = z >> 4;
    int nr = g_cnt[which * BB + b];
    int r0 = blockIdx.y * 64;
    if (r0 >= nr) return;
    int c0 = blockIdx.x * 128;
    const float* __restrict__ W    = which ? Wk : Wq;
    const float* __restrict__ bias = which ? bk : bq;
    const int*   __restrict__ idx  = which ? g_idx1 : g_idx0;
    float*       __restrict__ out  = which ? g_k : g_q;

    extern __shared__ __align__(16) uint16_t dyn[];
    __shared__ int sidx[64];

    int t = threadIdx.x;
    if (t < 64) sidx[t] = idx[b * SS + min(r0 + t, nr - 1)];
    __syncthreads();

    int lrow = t >> 3;            // 0..31
    int seg  = t & 7;             // 0..7
    const float* Eb = E + (size_t)b * SS * DD;
    const float* ap[2];
    const float* bp[4];
    #pragma unroll
    for (int i = 0; i < 2; i++)
        ap[i] = Eb + (size_t)sidx[lrow + i * 32] * DD + seg * 4;
    #pragma unroll
    for (int i = 0; i < 4; i++)
        bp[i] = W + (size_t)(c0 + lrow + i * 32) * DD + seg * 4;

    int wid = t >> 5, lane = t & 31;
    int wy = wid >> 2, wx = wid & 3;
    int grp = lane >> 2, qd = lane & 3;

    uint32_t dynBase = smem_addr(dyn);
    int aRow = lane & 15;
    int aK   = (lane >> 4) * 8;
    int bRow = (lane >> 4) * 8 + (lane & 7);
    int bK   = ((lane >> 3) & 1) * 8;

    float acc[2][4][4];
    #pragma unroll
    for (int mt = 0; mt < 2; mt++)
        #pragma unroll
        for (int nt = 0; nt < 4; nt++)
            #pragma unroll
            for (int r = 0; r < 4; r++) acc[mt][nt][r] = 0.f;

    float4 va[2], vb[4];
    #pragma unroll
    for (int i = 0; i < 2; i++) va[i] = *(const float4*)ap[i];
    #pragma unroll
    for (int i = 0; i < 4; i++) vb[i] = *(const float4*)bp[i];

    {
        uint16_t* Ah = dyn;
        uint16_t* Al = dyn + 64 * STR;
        uint16_t* Bh = dyn + 128 * STR;
        uint16_t* Bl = dyn + 256 * STR;
        #pragma unroll
        for (int i = 0; i < 2; i++) split_store(Ah, Al, lrow + i * 32, seg, va[i]);
        #pragma unroll
        for (int i = 0; i < 4; i++) split_store(Bh, Bl, lrow + i * 32, seg, vb[i]);
    }
    __syncthreads();

    for (int c = 0; c < NCH; c++) {
        int cur = c & 1;
        if (c + 1 < NCH) {
            int k0 = (c + 1) * BK;
            #pragma unroll
            for (int i = 0; i < 2; i++) va[i] = *(const float4*)(ap[i] + k0);
            #pragma unroll
            for (int i = 0; i < 4; i++) vb[i] = *(const float4*)(bp[i] + k0);
        }

        uint32_t sb = dynBase + cur * PROJ_STAGE_B;
        uint32_t aBaseH = sb, aBaseL = sb + 64 * STR * 2;
        uint32_t bBaseH = sb + 128 * STR * 2, bBaseL = sb + 256 * STR * 2;

        #pragma unroll
        for (int ks = 0; ks < 2; ks++) {
            uint32_t bhf[4][2], blf[4][2];
            #pragma unroll
            for (int p = 0; p < 2; p++) {
                uint32_t off = (uint32_t)((wx * 32 + p * 16 + bRow) * STR + ks * 16 + bK) * 2;
                uint32_t tmp[4];
                ldsm4(tmp, bBaseH + off);
                bhf[2 * p][0] = tmp[0]; bhf[2 * p][1] = tmp[1];
                bhf[2 * p + 1][0] = tmp[2]; bhf[2 * p + 1][1] = tmp[3];
                ldsm4(tmp, bBaseL + off);
                blf[2 * p][0] = tmp[0]; blf[2 * p][1] = tmp[1];
                blf[2 * p + 1][0] = tmp[2]; blf[2 * p + 1][1] = tmp[3];
            }
            #pragma unroll
            for (int mt = 0; mt < 2; mt++) {
                uint32_t off = (uint32_t)((wy * 32 + mt * 16 + aRow) * STR + ks * 16 + aK) * 2;
                uint32_t ahf[4], alf[4];
                ldsm4(ahf, aBaseH + off);
                ldsm4(alf, aBaseL + off);
                #pragma unroll
                for (int nt = 0; nt < 4; nt++) {
                    mma16816(acc[mt][nt], ahf, bhf[nt]);
                    mma16816(acc[mt][nt], ahf, blf[nt]);
                    mma16816(acc[mt][nt], alf, bhf[nt]);
                }
            }
        }

        if (c + 1 < NCH) {
            uint16_t* stg = dyn + (cur ^ 1) * (PROJ_STAGE_B / 2);
            uint16_t* Ah = stg;
            uint16_t* Al = stg + 64 * STR;
            uint16_t* Bh = stg + 128 * STR;
            uint16_t* Bl = stg + 256 * STR;
            #pragma unroll
            for (int i = 0; i < 2; i++) split_store(Ah, Al, lrow + i * 32, seg, va[i]);
            #pragma unroll
            for (int i = 0; i < 4; i++) split_store(Bh, Bl, lrow + i * 32, seg, vb[i]);
        }
        __syncthreads();
    }

    #pragma unroll
    for (int mt = 0; mt < 2; mt++) {
        int rA = r0 + wy * 32 + mt * 16 + grp;
        #pragma unroll
        for (int nt = 0; nt < 4; nt++) {
            int col = c0 + wx * 32 + nt * 8 + qd * 2;
            float2 bv = *(const float2*)(bias + col);
            if (rA < nr) {
                float2 v0 = make_float2(acc[mt][nt][0] + bv.x, acc[mt][nt][1] + bv.y);
                *(float2*)(out + ((size_t)b * SS + rA) * DD + col) = v0;
            }
            if (rA + 8 < nr) {
                float2 v1 = make_float2(acc[mt][nt][2] + bv.x, acc[mt][nt][3] + bv.y);
                *(float2*)(out + ((size_t)b * SS + rA + 8) * DD + col) = v1;
            }
        }
    }
}

// -------------- bf16x3 pair partial GEMM (64x64 tiles, K-split x4) ----------
__global__ __launch_bounds__(256) void pair_partial(const float* __restrict__ E) {
    int z   = blockIdx.z;
    int b   = z & 15, ks4 = z >> 4;            // ks4: 0..KS-1
    int pid = blockIdx.y * 8 + blockIdx.x;
    int n0  = g_cnt[b], n1 = g_cnt[BB + b];
    int i0  = blockIdx.y * 64, j0 = blockIdx.x * 64;
    int tid = threadIdx.x;
    if (i0 >= n0 || j0 >= n1) return;

    __shared__ __align__(16) uint16_t Qh[64 * STR], Ql[64 * STR];
    __shared__ __align__(16) uint16_t Ih[64 * STR], Il[64 * STR];
    __shared__ __align__(16) uint16_t Kh[64 * STR], Kl[64 * STR];
    __shared__ __align__(16) uint16_t Jh[64 * STR], Jl[64 * STR];
    __shared__ int si[64], sj[64];

    if (tid < 64) {
        si[tid] = g_idx0[b * SS + min(i0 + tid, n0 - 1)];
        sj[tid] = g_idx1[b * SS + min(j0 + tid, n1 - 1)];
    }
    __syncthreads();

    int lrow = tid >> 3, seg = tid & 7;
    int kbase = ks4 * PCH * BK;                // start K offset for this split
    const float* Eb = E + (size_t)b * SS * DD;
    const float* qp[2]; const float* ip[2]; const float* kp[2]; const float* jp[2];
    #pragma unroll
    for (int i = 0; i < 2; i++) {
        int r = lrow + i * 32;
        qp[i] = g_q + ((size_t)b * SS + min(i0 + r, n0 - 1)) * DD + seg * 4 + kbase;
        ip[i] = Eb + (size_t)si[r] * DD + seg * 4 + kbase;
        kp[i] = g_k + ((size_t)b * SS + min(j0 + r, n1 - 1)) * DD + seg * 4 + kbase;
        jp[i] = Eb + (size_t)sj[r] * DD + seg * 4 + kbase;
    }

    int wid = tid >> 5, lane = tid & 31;
    int wy = wid >> 2, wx = wid & 3;

    uint32_t qBaseH = smem_addr(Qh), qBaseL = smem_addr(Ql);
    uint32_t iBaseH = smem_addr(Ih), iBaseL = smem_addr(Il);
    uint32_t kBaseH = smem_addr(Kh), kBaseL = smem_addr(Kl);
    uint32_t jBaseH = smem_addr(Jh), jBaseL = smem_addr(Jl);
    int aRow = lane & 15;
    int aK   = (lane >> 4) * 8;
    int bRow = (lane >> 4) * 8 + (lane & 7);
    int bK   = ((lane >> 3) & 1) * 8;

    float aL[2][2][4], aG[2][2][4];
    #pragma unroll
    for (int mt = 0; mt < 2; mt++)
        #pragma unroll
        for (int nt = 0; nt < 2; nt++)
            #pragma unroll
            for (int r = 0; r < 4; r++) { aL[mt][nt][r] = 0.f; aG[mt][nt][r] = 0.f; }

    float4 vq[2], vi[2], vk[2], vj[2];
    #pragma unroll
    for (int i = 0; i < 2; i++) {
        vq[i] = *(const float4*)qp[i];
        vi[i] = *(const float4*)ip[i];
        vk[i] = *(const float4*)kp[i];
        vj[i] = *(const float4*)jp[i];
    }

    for (int c = 0; c < PCH; c++) {
        #pragma unroll
        for (int i = 0; i < 2; i++) {
            int row = lrow + i * 32;
            split_store(Qh, Ql, row, seg, vq[i]);
            split_store(Ih, Il, row, seg, vi[i]);
            split_store(Kh, Kl, row, seg, vk[i]);
            split_store(Jh, Jl, row, seg, vj[i]);
        }
        __syncthreads();

        if (c < PCH - 1) {
            int k0 = (c + 1) * BK;
            #pragma unroll
            for (int i = 0; i < 2; i++) {
                vq[i] = *(const float4*)(qp[i] + k0);
                vi[i] = *(const float4*)(ip[i] + k0);
                vk[i] = *(const float4*)(kp[i] + k0);
                vj[i] = *(const float4*)(jp[i] + k0);
            }
        }

        #pragma unroll
        for (int ks = 0; ks < 2; ks++) {
            uint32_t boff = (uint32_t)((wx * 16 + bRow) * STR + ks * 16 + bK) * 2;
            uint32_t kbh[2][2], kbl[2][2], jbh[2][2], jbl[2][2];
            {
                uint32_t tmp[4];
                ldsm4(tmp, kBaseH + boff);
                kbh[0][0] = tmp[0]; kbh[0][1] = tmp[1]; kbh[1][0] = tmp[2]; kbh[1][1] = tmp[3];
                ldsm4(tmp, kBaseL + boff);
                kbl[0][0] = tmp[0]; kbl[0][1] = tmp[1]; kbl[1][0] = tmp[2]; kbl[1][1] = tmp[3];
                ldsm4(tmp, jBaseH + boff);
                jbh[0][0] = tmp[0]; jbh[0][1] = tmp[1]; jbh[1][0] = tmp[2]; jbh[1][1] = tmp[3];
                ldsm4(tmp, jBaseL + boff);
                jbl[0][0] = tmp[0]; jbl[0][1] = tmp[1]; jbl[1][0] = tmp[2]; jbl[1][1] = tmp[3];
            }
            #pragma unroll
            for (int mt = 0; mt < 2; mt++) {
                uint32_t aoff = (uint32_t)((wy * 32 + mt * 16 + aRow) * STR + ks * 16 + aK) * 2;
                uint32_t qah[4], qal[4], iah[4], ial[4];
                ldsm4(qah, qBaseH + aoff);
                ldsm4(qal, qBaseL + aoff);
                ldsm4(iah, iBaseH + aoff);
                ldsm4(ial, iBaseL + aoff);
                #pragma unroll
                for (int nt = 0; nt < 2; nt++) {
                    mma16816(aL[mt][nt], qah, kbh[nt]);
                    mma16816(aL[mt][nt], qah, kbl[nt]);
                    mma16816(aL[mt][nt], qal, kbh[nt]);
                    mma16816(aG[mt][nt], iah, jbh[nt]);
                    mma16816(aG[mt][nt], iah, jbl[nt]);
                    mma16816(aG[mt][nt], ial, jbh[nt]);
                }
            }
        }
        __syncthreads();
    }

    // write raw partial accumulators
    size_t off = ((size_t)(b * KS + ks4) * NPID + pid) * 4096 + tid * 16;
    #pragma unroll
    for (int mt = 0; mt < 2; mt++)
        #pragma unroll
        for (int nt = 0; nt < 2; nt++) {
            *(float4*)(g_partL + off + (mt * 2 + nt) * 4) = *(float4*)aL[mt][nt];
            *(float4*)(g_partG + off + (mt * 2 + nt) * 4) = *(float4*)aG[mt][nt];
        }
}

// --------------- combine K-split partials + mask + online softmax -----------
__global__ __launch_bounds__(256) void pair_combine() {
    int b   = blockIdx.z;
    int pid = blockIdx.y * 8 + blockIdx.x;
    int n0  = g_cnt[b], n1 = g_cnt[BB + b];
    int i0  = blockIdx.y * 64, j0 = blockIdx.x * 64;
    int tid = threadIdx.x;
    if (i0 >= n0 || j0 >= n1) {
        if (tid == 0) {
            g_pm[b * NPID + pid] = NEG_BIG;
            g_pl[b * NPID + pid] = 0.f;
            g_pa[b * NPID + pid] = 0.f;
        }
        return;
    }

    __shared__ float sinvi[64], sinvj[64];
    if (tid < 64) {
        sinvi[tid] = g_invn[b * SS + g_idx0[b * SS + min(i0 + tid, n0 - 1)]];
        sinvj[tid] = g_invn[b * SS + g_idx1[b * SS + min(j0 + tid, n1 - 1)]];
    }
    __syncthreads();

    int wid = tid >> 5, lane = tid & 31;
    int wy = wid >> 2, wx = wid & 3;
    int grp = lane >> 2, qd = lane & 3;

    float aL[2][2][4], aG[2][2][4];
    #pragma unroll
    for (int mt = 0; mt < 2; mt++)
        #pragma unroll
        for (int nt = 0; nt < 2; nt++)
            #pragma unroll
            for (int r = 0; r < 4; r++) { aL[mt][nt][r] = 0.f; aG[mt][nt][r] = 0.f; }

    #pragma unroll
    for (int s = 0; s < KS; s++) {
        size_t off = ((size_t)(b * KS + s) * NPID + pid) * 4096 + tid * 16;
        #pragma unroll
        for (int mt = 0; mt < 2; mt++)
            #pragma unroll
            for (int nt = 0; nt < 2; nt++) {
                float4 vL = *(const float4*)(g_partL + off + (mt * 2 + nt) * 4);
                float4 vG = *(const float4*)(g_partG + off + (mt * 2 + nt) * 4);
                aL[mt][nt][0] += vL.x; aL[mt][nt][1] += vL.y;
                aL[mt][nt][2] += vL.z; aL[mt][nt][3] += vL.w;
                aG[mt][nt][0] += vG.x; aG[mt][nt][1] += vG.y;
                aG[mt][nt][2] += vG.z; aG[mt][nt][3] += vG.w;
            }
    }

    float m = NEG_BIG, l = 0.f, a = 0.f;
    #pragma unroll
    for (int mt = 0; mt < 2; mt++)
        #pragma unroll
        for (int nt = 0; nt < 2; nt++)
            #pragma unroll
            for (int rr = 0; rr < 2; rr++)
                #pragma unroll
                for (int cc = 0; cc < 2; cc++) {
                    int li = wy * 32 + mt * 16 + grp + rr * 8;
                    int lj = wx * 16 + nt * 8 + qd * 2 + cc;
                    if (i0 + li < n0 && j0 + lj < n1)
                        m = fmaxf(m, aL[mt][nt][rr * 2 + cc]);
                }
    if (m > NEG_BIG * 0.5f) {
        #pragma unroll
        for (int mt = 0; mt < 2; mt++)
            #pragma unroll
            for (int nt = 0; nt < 2; nt++)
                #pragma unroll
                for (int rr = 0; rr < 2; rr++)
                    #pragma unroll
                    for (int cc = 0; cc < 2; cc++) {
                        int li = wy * 32 + mt * 16 + grp + rr * 8;
                        int lj = wx * 16 + nt * 8 + qd * 2 + cc;
                        if (i0 + li < n0 && j0 + lj < n1) {
                            float w  = expf(aL[mt][nt][rr * 2 + cc] - m);
                            float sc = fabsf(aG[mt][nt][rr * 2 + cc]) * sinvi[li] * sinvj[lj];
                            l += w;
                            a += w * sc;
                        }
                    }
    }

    __shared__ float rm_[256], rl_[256], ra_[256];
    rm_[tid] = m; rl_[tid] = l; ra_[tid] = a;
    __syncthreads();
    for (int s = 128; s > 0; s >>= 1) {
        if (tid < s) {
            float M = rm_[tid], L = rl_[tid], A = ra_[tid];
            softmax_merge(M, L, A, rm_[tid + s], rl_[tid + s], ra_[tid + s]);
            rm_[tid] = M; rl_[tid] = L; ra_[tid] = A;
        }
        __syncthreads();
    }
    if (tid == 0) {
        g_pm[b * NPID + pid] = rm_[0];
        g_pl[b * NPID + pid] = rl_[0];
        g_pa[b * NPID + pid] = ra_[0];
    }
}

// ------------------------------------------------------------------ finalize --
__global__ void finalize(float* __restrict__ out) {
    int b = blockIdx.x;
    int t = threadIdx.x;   // 64 threads
    __shared__ float sm[64], sl[64], sa[64];
    sm[t] = g_pm[b * NPID + t];
    sl[t] = g_pl[b * NPID + t];
    sa[t] = g_pa[b * NPID + t];
    __syncthreads();
    for (int s = 32; s > 0; s >>= 1) {
        if (t < s) {
            float M = sm[t], L = sl[t], A = sa[t];
            softmax_merge(M, L, A, sm[t + s], sl[t + s], sa[t + s]);
            sm[t] = M; sl[t] = L; sa[t] = A;
        }
        __syncthreads();
    }
    if (t == 0) out[b] = (sl[0] > 0.f) ? (sa[0] / sl[0]) : 0.f;
}

// -------------------------------------------------------------------- launch --
extern "C" void kernel_launch(void* const* d_in, const int* in_sizes, int n_in,
                              void* d_out, int out_size) {
    const float* E  = (const float*)d_in[0];
    const float* Wq = (const float*)d_in[1];
    const float* bq = (const float*)d_in[2];
    const float* Wk = (const float*)d_in[3];
    const float* bk = (const float*)d_in[4];
    const int*   am = (const int*)d_in[5];
    const int*   tt = (const int*)d_in[6];
    float* out = (float*)d_out;

    cudaFuncSetAttribute(proj_mma, cudaFuncAttributeMaxDynamicSharedMemorySize,
                         PROJ_SMEM);

    prep_and_norms<<<NTOK / 16, 512>>>(E, am, tt);
    proj_mma<<<dim3(8, 8, 2 * BB), 256, PROJ_SMEM>>>(E, Wq, bq, Wk, bk);
    pair_partial<<<dim3(8, 8, BB * KS), 256>>>(E);
    pair_combine<<<dim3(8, 8, BB), 256>>>();
    finalize<<<BB, 64>>>(out);
}

// round 13
// speedup vs baseline: 1.5235x; 1.5235x over previous
#include <cuda_runtime.h>
#include <cuda_bf16.h>
#include <math.h>
#include <stdint.h>

#define BB 16
#define SS 512
#define DD 1024
#define NTOK (BB*SS)
#define NEG_BIG (-3.0e38f)
#define NPID 64
#define KS 4               // K-splits for pair phase
#define BK 32
#define NCH (DD / BK)
#define PCH (NCH / KS)     // chunks per pair K-split = 8
#define STR 40             // smem row stride in bf16 elems (80B, LDSM conflict-free)

// ------------------------------ scratch (static device globals; no allocs) --
__device__ float g_q[(size_t)NTOK * DD];
__device__ float g_k[(size_t)NTOK * DD];
__device__ float g_invn[NTOK];
__device__ int   g_idx0[NTOK];
__device__ int   g_idx1[NTOK];
__device__ int   g_cnt[2 * BB];
__device__ float g_pm[BB * NPID];
__device__ float g_pl[BB * NPID];
__device__ float g_pa[BB * NPID];
__device__ float g_partL[(size_t)BB * KS * NPID * 4096];
__device__ float g_partG[(size_t)BB * KS * NPID * 4096];

__device__ __forceinline__ void softmax_merge(float& m1, float& l1, float& a1,
                                              float m2, float l2, float a2) {
    float M  = fmaxf(m1, m2);
    float e1 = (l1 > 0.f) ? expf(m1 - M) : 0.f;
    float e2 = (l2 > 0.f) ? expf(m2 - M) : 0.f;
    l1 = l1 * e1 + l2 * e2;
    a1 = a1 * e1 + a2 * e2;
    m1 = M;
}

__device__ __forceinline__ uint32_t pack_bf2(float x, float y) {
    __nv_bfloat162 h = __floats2bfloat162_rn(x, y);
    return *(uint32_t*)&h;
}
__device__ __forceinline__ void mma16816(float* c, const uint32_t* a, const uint32_t* b) {
    asm volatile(
        "mma.sync.aligned.m16n8k16.row.col.f32.bf16.bf16.f32 "
        "{%0,%1,%2,%3}, {%4,%5,%6,%7}, {%8,%9}, {%0,%1,%2,%3};"
        : "+f"(c[0]), "+f"(c[1]), "+f"(c[2]), "+f"(c[3])
        : "r"(a[0]), "r"(a[1]), "r"(a[2]), "r"(a[3]), "r"(b[0]), "r"(b[1]));
}
__device__ __forceinline__ void ldsm4(uint32_t* r, uint32_t addr) {
    asm volatile("ldmatrix.sync.aligned.m8n8.x4.shared.b16 {%0,%1,%2,%3}, [%4];"
        : "=r"(r[0]), "=r"(r[1]), "=r"(r[2]), "=r"(r[3]) : "r"(addr));
}
__device__ __forceinline__ uint32_t smem_addr(const void* p) {
    return (uint32_t)__cvta_generic_to_shared(p);
}
__device__ __forceinline__ void split_store(uint16_t* hB, uint16_t* lB,
                                            int row, int seg, float4 v) {
    uint32_t h01 = pack_bf2(v.x, v.y), h23 = pack_bf2(v.z, v.w);
    __nv_bfloat162 a01 = *(__nv_bfloat162*)&h01, a23 = *(__nv_bfloat162*)&h23;
    uint32_t l01 = pack_bf2(v.x - __bfloat162float(a01.x), v.y - __bfloat162float(a01.y));
    uint32_t l23 = pack_bf2(v.z - __bfloat162float(a23.x), v.w - __bfloat162float(a23.y));
    uint32_t* dh = (uint32_t*)(hB + row * STR + seg * 4);
    uint32_t* dl = (uint32_t*)(lB + row * STR + seg * 4);
    dh[0] = h01; dh[1] = h23;
    dl[0] = l01; dl[1] = l23;
}

// ---------------------------------------------------------- mask compaction --
__global__ void prep_masks(const int* __restrict__ am, const int* __restrict__ tt) {
    int b = blockIdx.x;
    int t = threadIdx.x;
    int lane = t & 31, w = t >> 5;
    int a  = am[b * SS + t];
    int ty = tt[b * SS + t];
    bool f0 = (a == 1) && (ty == 0);
    bool f1 = (a == 1) && (ty == 1);
    unsigned bal0 = __ballot_sync(0xffffffffu, f0);
    unsigned bal1 = __ballot_sync(0xffffffffu, f1);
    __shared__ int wc0[16], wc1[16], off0[16], off1[16];
    if (lane == 0) { wc0[w] = __popc(bal0); wc1[w] = __popc(bal1); }
    __syncthreads();
    if (t == 0) {
        int s0 = 0, s1 = 0;
        for (int i = 0; i < 16; i++) {
            off0[i] = s0; s0 += wc0[i];
            off1[i] = s1; s1 += wc1[i];
        }
        g_cnt[b] = s0; g_cnt[BB + b] = s1;
    }
    __syncthreads();
    if (f0) g_idx0[b * SS + off0[w] + __popc(bal0 & ((1u << lane) - 1u))] = t;
    if (f1) g_idx1[b * SS + off1[w] + __popc(bal1 & ((1u << lane) - 1u))] = t;
}

// -------------------------------------------------- row inv-norms (warp/row) --
__global__ __launch_bounds__(512) void row_norms(const float* __restrict__ E) {
    int row  = blockIdx.x * 16 + (threadIdx.x >> 5);
    int lane = threadIdx.x & 31;
    const float4* p = (const float4*)(E + (size_t)row * DD);
    float s = 0.f;
    #pragma unroll
    for (int i = 0; i < 8; i++) {
        float4 v = p[lane + i * 32];
        s += v.x * v.x + v.y * v.y + v.z * v.z + v.w * v.w;
    }
    #pragma unroll
    for (int o = 16; o > 0; o >>= 1) s += __shfl_down_sync(0xffffffffu, s, o);
    if (lane == 0) g_invn[row] = 1.f / fmaxf(sqrtf(s), 1e-12f);
}

// ---- mma.sync bf16x3 gathered projection GEMM (64-row tiles, double-buffer) --
#define PROJ_STAGE_B 30720            // bytes per stage: (64+64+128+128)*STR*2
#define PROJ_SMEM (2 * PROJ_STAGE_B)  // 61440

__global__ __launch_bounds__(256) void proj_mma(
    const float* __restrict__ E,
    const float* __restrict__ Wq, const float* __restrict__ bq,
    const float* __restrict__ Wk, const float* __restrict__ bk)
{
    int z = blockIdx.z;
    int b = z & 15, which = z >> 4;
    int nr = g_cnt[which * BB + b];
    int r0 = blockIdx.y * 64;
    if (r0 >= nr) return;
    int c0 = blockIdx.x * 128;
    const float* __restrict__ W    = which ? Wk : Wq;
    const float* __restrict__ bias = which ? bk : bq;
    const int*   __restrict__ idx  = which ? g_idx1 : g_idx0;
    float*       __restrict__ out  = which ? g_k : g_q;

    extern __shared__ __align__(16) uint16_t dyn[];
    __shared__ int sidx[64];

    int t = threadIdx.x;
    if (t < 64) sidx[t] = idx[b * SS + min(r0 + t, nr - 1)];
    __syncthreads();

    int lrow = t >> 3;            // 0..31
    int seg  = t & 7;             // 0..7
    const float* Eb = E + (size_t)b * SS * DD;
    const float* ap[2];
    const float* bp[4];
    #pragma unroll
    for (int i = 0; i < 2; i++)
        ap[i] = Eb + (size_t)sidx[lrow + i * 32] * DD + seg * 4;
    #pragma unroll
    for (int i = 0; i < 4; i++)
        bp[i] = W + (size_t)(c0 + lrow + i * 32) * DD + seg * 4;

    int wid = t >> 5, lane = t & 31;
    int wy = wid >> 2, wx = wid & 3;
    int grp = lane >> 2, qd = lane & 3;

    uint32_t dynBase = smem_addr(dyn);
    int aRow = lane & 15;
    int aK   = (lane >> 4) * 8;
    int bRow = (lane >> 4) * 8 + (lane & 7);
    int bK   = ((lane >> 3) & 1) * 8;

    float acc[2][4][4];
    #pragma unroll
    for (int mt = 0; mt < 2; mt++)
        #pragma unroll
        for (int nt = 0; nt < 4; nt++)
            #pragma unroll
            for (int r = 0; r < 4; r++) acc[mt][nt][r] = 0.f;

    float4 va[2], vb[4];
    #pragma unroll
    for (int i = 0; i < 2; i++) va[i] = *(const float4*)ap[i];
    #pragma unroll
    for (int i = 0; i < 4; i++) vb[i] = *(const float4*)bp[i];

    {
        uint16_t* Ah = dyn;
        uint16_t* Al = dyn + 64 * STR;
        uint16_t* Bh = dyn + 128 * STR;
        uint16_t* Bl = dyn + 256 * STR;
        #pragma unroll
        for (int i = 0; i < 2; i++) split_store(Ah, Al, lrow + i * 32, seg, va[i]);
        #pragma unroll
        for (int i = 0; i < 4; i++) split_store(Bh, Bl, lrow + i * 32, seg, vb[i]);
    }
    __syncthreads();

    for (int c = 0; c < NCH; c++) {
        int cur = c & 1;
        if (c + 1 < NCH) {
            int k0 = (c + 1) * BK;
            #pragma unroll
            for (int i = 0; i < 2; i++) va[i] = *(const float4*)(ap[i] + k0);
            #pragma unroll
            for (int i = 0; i < 4; i++) vb[i] = *(const float4*)(bp[i] + k0);
        }

        uint32_t sb = dynBase + cur * PROJ_STAGE_B;
        uint32_t aBaseH = sb, aBaseL = sb + 64 * STR * 2;
        uint32_t bBaseH = sb + 128 * STR * 2, bBaseL = sb + 256 * STR * 2;

        #pragma unroll
        for (int ks = 0; ks < 2; ks++) {
            uint32_t bhf[4][2], blf[4][2];
            #pragma unroll
            for (int p = 0; p < 2; p++) {
                uint32_t off = (uint32_t)((wx * 32 + p * 16 + bRow) * STR + ks * 16 + bK) * 2;
                uint32_t tmp[4];
                ldsm4(tmp, bBaseH + off);
                bhf[2 * p][0] = tmp[0]; bhf[2 * p][1] = tmp[1];
                bhf[2 * p + 1][0] = tmp[2]; bhf[2 * p + 1][1] = tmp[3];
                ldsm4(tmp, bBaseL + off);
                blf[2 * p][0] = tmp[0]; blf[2 * p][1] = tmp[1];
                blf[2 * p + 1][0] = tmp[2]; blf[2 * p + 1][1] = tmp[3];
            }
            #pragma unroll
            for (int mt = 0; mt < 2; mt++) {
                uint32_t off = (uint32_t)((wy * 32 + mt * 16 + aRow) * STR + ks * 16 + aK) * 2;
                uint32_t ahf[4], alf[4];
                ldsm4(ahf, aBaseH + off);
                ldsm4(alf, aBaseL + off);
                #pragma unroll
                for (int nt = 0; nt < 4; nt++) {
                    mma16816(acc[mt][nt], ahf, bhf[nt]);
                    mma16816(acc[mt][nt], ahf, blf[nt]);
                    mma16816(acc[mt][nt], alf, bhf[nt]);
                }
            }
        }

        if (c + 1 < NCH) {
            uint16_t* stg = dyn + (cur ^ 1) * (PROJ_STAGE_B / 2);
            uint16_t* Ah = stg;
            uint16_t* Al = stg + 64 * STR;
            uint16_t* Bh = stg + 128 * STR;
            uint16_t* Bl = stg + 256 * STR;
            #pragma unroll
            for (int i = 0; i < 2; i++) split_store(Ah, Al, lrow + i * 32, seg, va[i]);
            #pragma unroll
            for (int i = 0; i < 4; i++) split_store(Bh, Bl, lrow + i * 32, seg, vb[i]);
        }
        __syncthreads();
    }

    #pragma unroll
    for (int mt = 0; mt < 2; mt++) {
        int rA = r0 + wy * 32 + mt * 16 + grp;
        #pragma unroll
        for (int nt = 0; nt < 4; nt++) {
            int col = c0 + wx * 32 + nt * 8 + qd * 2;
            float2 bv = *(const float2*)(bias + col);
            if (rA < nr) {
                float2 v0 = make_float2(acc[mt][nt][0] + bv.x, acc[mt][nt][1] + bv.y);
                *(float2*)(out + ((size_t)b * SS + rA) * DD + col) = v0;
            }
            if (rA + 8 < nr) {
                float2 v1 = make_float2(acc[mt][nt][2] + bv.x, acc[mt][nt][3] + bv.y);
                *(float2*)(out + ((size_t)b * SS + rA + 8) * DD + col) = v1;
            }
        }
    }
}

// -------------- bf16x3 pair partial GEMM (64x64 tiles, K-split x4) ----------
__global__ __launch_bounds__(256) void pair_partial(const float* __restrict__ E) {
    int z   = blockIdx.z;
    int b   = z & 15, ks4 = z >> 4;            // ks4: 0..KS-1
    int pid = blockIdx.y * 8 + blockIdx.x;
    int n0  = g_cnt[b], n1 = g_cnt[BB + b];
    int i0  = blockIdx.y * 64, j0 = blockIdx.x * 64;
    int tid = threadIdx.x;
    if (i0 >= n0 || j0 >= n1) return;

    __shared__ __align__(16) uint16_t Qh[64 * STR], Ql[64 * STR];
    __shared__ __align__(16) uint16_t Ih[64 * STR], Il[64 * STR];
    __shared__ __align__(16) uint16_t Kh[64 * STR], Kl[64 * STR];
    __shared__ __align__(16) uint16_t Jh[64 * STR], Jl[64 * STR];
    __shared__ int si[64], sj[64];

    if (tid < 64) {
        si[tid] = g_idx0[b * SS + min(i0 + tid, n0 - 1)];
        sj[tid] = g_idx1[b * SS + min(j0 + tid, n1 - 1)];
    }
    __syncthreads();

    int lrow = tid >> 3, seg = tid & 7;
    int kbase = ks4 * PCH * BK;                // start K offset for this split
    const float* Eb = E + (size_t)b * SS * DD;
    const float* qp[2]; const float* ip[2]; const float* kp[2]; const float* jp[2];
    #pragma unroll
    for (int i = 0; i < 2; i++) {
        int r = lrow + i * 32;
        qp[i] = g_q + ((size_t)b * SS + min(i0 + r, n0 - 1)) * DD + seg * 4 + kbase;
        ip[i] = Eb + (size_t)si[r] * DD + seg * 4 + kbase;
        kp[i] = g_k + ((size_t)b * SS + min(j0 + r, n1 - 1)) * DD + seg * 4 + kbase;
        jp[i] = Eb + (size_t)sj[r] * DD + seg * 4 + kbase;
    }

    int wid = tid >> 5, lane = tid & 31;
    int wy = wid >> 2, wx = wid & 3;

    uint32_t qBaseH = smem_addr(Qh), qBaseL = smem_addr(Ql);
    uint32_t iBaseH = smem_addr(Ih), iBaseL = smem_addr(Il);
    uint32_t kBaseH = smem_addr(Kh), kBaseL = smem_addr(Kl);
    uint32_t jBaseH = smem_addr(Jh), jBaseL = smem_addr(Jl);
    int aRow = lane & 15;
    int aK   = (lane >> 4) * 8;
    int bRow = (lane >> 4) * 8 + (lane & 7);
    int bK   = ((lane >> 3) & 1) * 8;

    float aL[2][2][4], aG[2][2][4];
    #pragma unroll
    for (int mt = 0; mt < 2; mt++)
        #pragma unroll
        for (int nt = 0; nt < 2; nt++)
            #pragma unroll
            for (int r = 0; r < 4; r++) { aL[mt][nt][r] = 0.f; aG[mt][nt][r] = 0.f; }

    float4 vq[2], vi[2], vk[2], vj[2];
    #pragma unroll
    for (int i = 0; i < 2; i++) {
        vq[i] = *(const float4*)qp[i];
        vi[i] = *(const float4*)ip[i];
        vk[i] = *(const float4*)kp[i];
        vj[i] = *(const float4*)jp[i];
    }

    for (int c = 0; c < PCH; c++) {
        #pragma unroll
        for (int i = 0; i < 2; i++) {
            int row = lrow + i * 32;
            split_store(Qh, Ql, row, seg, vq[i]);
            split_store(Ih, Il, row, seg, vi[i]);
            split_store(Kh, Kl, row, seg, vk[i]);
            split_store(Jh, Jl, row, seg, vj[i]);
        }
        __syncthreads();

        if (c < PCH - 1) {
            int k0 = (c + 1) * BK;
            #pragma unroll
            for (int i = 0; i < 2; i++) {
                vq[i] = *(const float4*)(qp[i] + k0);
                vi[i] = *(const float4*)(ip[i] + k0);
                vk[i] = *(const float4*)(kp[i] + k0);
                vj[i] = *(const float4*)(jp[i] + k0);
            }
        }

        #pragma unroll
        for (int ks = 0; ks < 2; ks++) {
            uint32_t boff = (uint32_t)((wx * 16 + bRow) * STR + ks * 16 + bK) * 2;
            uint32_t kbh[2][2], kbl[2][2], jbh[2][2], jbl[2][2];
            {
                uint32_t tmp[4];
                ldsm4(tmp, kBaseH + boff);
                kbh[0][0] = tmp[0]; kbh[0][1] = tmp[1]; kbh[1][0] = tmp[2]; kbh[1][1] = tmp[3];
                ldsm4(tmp, kBaseL + boff);
                kbl[0][0] = tmp[0]; kbl[0][1] = tmp[1]; kbl[1][0] = tmp[2]; kbl[1][1] = tmp[3];
                ldsm4(tmp, jBaseH + boff);
                jbh[0][0] = tmp[0]; jbh[0][1] = tmp[1]; jbh[1][0] = tmp[2]; jbh[1][1] = tmp[3];
                ldsm4(tmp, jBaseL + boff);
                jbl[0][0] = tmp[0]; jbl[0][1] = tmp[1]; jbl[1][0] = tmp[2]; jbl[1][1] = tmp[3];
            }
            #pragma unroll
            for (int mt = 0; mt < 2; mt++) {
                uint32_t aoff = (uint32_t)((wy * 32 + mt * 16 + aRow) * STR + ks * 16 + aK) * 2;
                uint32_t qah[4], qal[4], iah[4], ial[4];
                ldsm4(qah, qBaseH + aoff);
                ldsm4(qal, qBaseL + aoff);
                ldsm4(iah, iBaseH + aoff);
                ldsm4(ial, iBaseL + aoff);
                #pragma unroll
                for (int nt = 0; nt < 2; nt++) {
                    mma16816(aL[mt][nt], qah, kbh[nt]);
                    mma16816(aL[mt][nt], qah, kbl[nt]);
                    mma16816(aL[mt][nt], qal, kbh[nt]);
                    mma16816(aG[mt][nt], iah, jbh[nt]);
                    mma16816(aG[mt][nt], iah, jbl[nt]);
                    mma16816(aG[mt][nt], ial, jbh[nt]);
                }
            }
        }
        __syncthreads();
    }

    // write raw partial accumulators
    size_t off = ((size_t)(b * KS + ks4) * NPID + pid) * 4096 + tid * 16;
    #pragma unroll
    for (int mt = 0; mt < 2; mt++)
        #pragma unroll
        for (int nt = 0; nt < 2; nt++) {
            *(float4*)(g_partL + off + (mt * 2 + nt) * 4) = *(float4*)aL[mt][nt];
            *(float4*)(g_partG + off + (mt * 2 + nt) * 4) = *(float4*)aG[mt][nt];
        }
}

// --------------- combine K-split partials + mask + online softmax -----------
__global__ __launch_bounds__(256) void pair_combine() {
    int b   = blockIdx.z;
    int pid = blockIdx.y * 8 + blockIdx.x;
    int n0  = g_cnt[b], n1 = g_cnt[BB + b];
    int i0  = blockIdx.y * 64, j0 = blockIdx.x * 64;
    int tid = threadIdx.x;
    if (i0 >= n0 || j0 >= n1) {
        if (tid == 0) {
            g_pm[b * NPID + pid] = NEG_BIG;
            g_pl[b * NPID + pid] = 0.f;
            g_pa[b * NPID + pid] = 0.f;
        }
        return;
    }

    __shared__ float sinvi[64], sinvj[64];
    if (tid < 64) {
        sinvi[tid] = g_invn[b * SS + g_idx0[b * SS + min(i0 + tid, n0 - 1)]];
        sinvj[tid] = g_invn[b * SS + g_idx1[b * SS + min(j0 + tid, n1 - 1)]];
    }
    __syncthreads();

    int wid = tid >> 5, lane = tid & 31;
    int wy = wid >> 2, wx = wid & 3;
    int grp = lane >> 2, qd = lane & 3;

    float aL[2][2][4], aG[2][2][4];
    #pragma unroll
    for (int mt = 0; mt < 2; mt++)
        #pragma unroll
        for (int nt = 0; nt < 2; nt++)
            #pragma unroll
            for (int r = 0; r < 4; r++) { aL[mt][nt][r] = 0.f; aG[mt][nt][r] = 0.f; }

    #pragma unroll
    for (int s = 0; s < KS; s++) {
        size_t off = ((size_t)(b * KS + s) * NPID + pid) * 4096 + tid * 16;
        #pragma unroll
        for (int mt = 0; mt < 2; mt++)
            #pragma unroll
            for (int nt = 0; nt < 2; nt++) {
                float4 vL = *(const float4*)(g_partL + off + (mt * 2 + nt) * 4);
                float4 vG = *(const float4*)(g_partG + off + (mt * 2 + nt) * 4);
                aL[mt][nt][0] += vL.x; aL[mt][nt][1] += vL.y;
                aL[mt][nt][2] += vL.z; aL[mt][nt][3] += vL.w;
                aG[mt][nt][0] += vG.x; aG[mt][nt][1] += vG.y;
                aG[mt][nt][2] += vG.z; aG[mt][nt][3] += vG.w;
            }
    }

    float m = NEG_BIG, l = 0.f, a = 0.f;
    #pragma unroll
    for (int mt = 0; mt < 2; mt++)
        #pragma unroll
        for (int nt = 0; nt < 2; nt++)
            #pragma unroll
            for (int rr = 0; rr < 2; rr++)
                #pragma unroll
                for (int cc = 0; cc < 2; cc++) {
                    int li = wy * 32 + mt * 16 + grp + rr * 8;
                    int lj = wx * 16 + nt * 8 + qd * 2 + cc;
                    if (i0 + li < n0 && j0 + lj < n1)
                        m = fmaxf(m, aL[mt][nt][rr * 2 + cc]);
                }
    if (m > NEG_BIG * 0.5f) {
        #pragma unroll
        for (int mt = 0; mt < 2; mt++)
            #pragma unroll
            for (int nt = 0; nt < 2; nt++)
                #pragma unroll
                for (int rr = 0; rr < 2; rr++)
                    #pragma unroll
                    for (int cc = 0; cc < 2; cc++) {
                        int li = wy * 32 + mt * 16 + grp + rr * 8;
                        int lj = wx * 16 + nt * 8 + qd * 2 + cc;
                        if (i0 + li < n0 && j0 + lj < n1) {
                            float w  = expf(aL[mt][nt][rr * 2 + cc] - m);
                            float sc = fabsf(aG[mt][nt][rr * 2 + cc]) * sinvi[li] * sinvj[lj];
                            l += w;
                            a += w * sc;
                        }
                    }
    }

    __shared__ float rm_[256], rl_[256], ra_[256];
    rm_[tid] = m; rl_[tid] = l; ra_[tid] = a;
    __syncthreads();
    for (int s = 128; s > 0; s >>= 1) {
        if (tid < s) {
            float M = rm_[tid], L = rl_[tid], A = ra_[tid];
            softmax_merge(M, L, A, rm_[tid + s], rl_[tid + s], ra_[tid + s]);
            rm_[tid] = M; rl_[tid] = L; ra_[tid] = A;
        }
        __syncthreads();
    }
    if (tid == 0) {
        g_pm[b * NPID + pid] = rm_[0];
        g_pl[b * NPID + pid] = rl_[0];
        g_pa[b * NPID + pid] = ra_[0];
    }
}

// ------------------------------------------------------------------ finalize --
__global__ void finalize(float* __restrict__ out) {
    int b = blockIdx.x;
    int t = threadIdx.x;   // 64 threads
    __shared__ float sm[64], sl[64], sa[64];
    sm[t] = g_pm[b * NPID + t];
    sl[t] = g_pl[b * NPID + t];
    sa[t] = g_pa[b * NPID + t];
    __syncthreads();
    for (int s = 32; s > 0; s >>= 1) {
        if (t < s) {
            float M = sm[t], L = sl[t], A = sa[t];
            softmax_merge(M, L, A, sm[t + s], sl[t + s], sa[t + s]);
            sm[t] = M; sl[t] = L; sa[t] = A;
        }
        __syncthreads();
    }
    if (t == 0) out[b] = (sl[0] > 0.f) ? (sa[0] / sl[0]) : 0.f;
}

// -------------------------------------------------------------------- launch --
extern "C" void kernel_launch(void* const* d_in, const int* in_sizes, int n_in,
                              void* d_out, int out_size) {
    const float* E  = (const float*)d_in[0];
    const float* Wq = (const float*)d_in[1];
    const float* bq = (const float*)d_in[2];
    const float* Wk = (const float*)d_in[3];
    const float* bk = (const float*)d_in[4];
    const int*   am = (const int*)d_in[5];
    const int*   tt = (const int*)d_in[6];
    float* out = (float*)d_out;

    cudaFuncSetAttribute(proj_mma, cudaFuncAttributeMaxDynamicSharedMemorySize,
                         PROJ_SMEM);

    prep_masks<<<BB, 512>>>(am, tt);
    row_norms<<<NTOK / 16, 512>>>(E);
    proj_mma<<<dim3(8, 8, 2 * BB), 256, PROJ_SMEM>>>(E, Wq, bq, Wk, bk);
    pair_partial<<<dim3(8, 8, BB * KS), 256>>>(E);
    pair_combine<<<dim3(8, 8, BB), 256>>>();
    finalize<<<BB, 64>>>(out);
}